// round 17
// baseline (speedup 1.0000x reference)
#include <cuda_runtime.h>
#include <cuda_bf16.h>
#include <cstdint>

typedef unsigned long long ull;

#define SEQ   2048
#define BATCH 64
#define KIN   256
#define HID   256
#define G4H   1024   // 4*HID
#define MTOT  (SEQ * BATCH)   // 131072

// ---------------- scratch (device globals; no allocation allowed) ----------
__device__ float g_preact[(size_t)SEQ * BATCH * G4H];          // 512 MB
__device__ __nv_bfloat16 g_xh[(size_t)MTOT * KIN];             // 64 MB
__device__ __nv_bfloat16 g_xl[(size_t)MTOT * KIN];             // 64 MB
__device__ __nv_bfloat16 g_wih[(size_t)G4H * KIN];
__device__ __nv_bfloat16 g_wil[(size_t)G4H * KIN];
__device__ float g_bias[G4H];
// tagged h exchange: [batch-slice][parity][b][j] = {u32 tag, f32 value}
__device__ __align__(16) ull g_hex[8][2][8][256];              // 256 KB
// per-timestep preact-ready flags (tag = t+1); cleared each launch
__device__ uint32_t g_pflag[SEQ];

// ---------------- small helpers -------------------------------------------
__device__ __forceinline__ uint32_t smem_u32(const void* p) {
    uint32_t a;
    asm("{ .reg .u64 t; cvta.to.shared.u64 t, %1; cvt.u32.u64 %0, t; }"
        : "=r"(a) : "l"(p));
    return a;
}
__device__ __forceinline__ float sigf(float x) {
    return __fdividef(1.f, 1.f + __expf(-x));
}
__device__ __forceinline__ float tanhf_(float x) { return 2.f * sigf(2.f * x) - 1.f; }

__device__ __forceinline__ void barn(int id, int cnt) {
    asm volatile("bar.sync %0, %1;" :: "r"(id), "r"(cnt) : "memory");
}
__device__ __forceinline__ void ldm_x4(uint32_t* r, uint32_t addr) {
    asm volatile("ldmatrix.sync.aligned.m8n8.x4.shared.b16 {%0,%1,%2,%3}, [%4];"
                 : "=r"(r[0]), "=r"(r[1]), "=r"(r[2]), "=r"(r[3]) : "r"(addr));
}
__device__ __forceinline__ void ldm_x2(uint32_t* r, uint32_t addr) {
    asm volatile("ldmatrix.sync.aligned.m8n8.x2.shared.b16 {%0,%1}, [%2];"
                 : "=r"(r[0]), "=r"(r[1]) : "r"(addr));
}
__device__ __forceinline__ void mma16816(float* d, const uint32_t* a,
                                         const uint32_t* b) {
    asm volatile(
        "mma.sync.aligned.m16n8k16.row.col.f32.bf16.bf16.f32 "
        "{%0,%1,%2,%3}, {%4,%5,%6,%7}, {%8,%9}, {%0,%1,%2,%3};"
        : "+f"(d[0]), "+f"(d[1]), "+f"(d[2]), "+f"(d[3])
        : "r"(a[0]), "r"(a[1]), "r"(a[2]), "r"(a[3]), "r"(b[0]), "r"(b[1]));
}

// cp.async primitives
__device__ __forceinline__ void cpa16(uint32_t dst, const void* src) {
    asm volatile("cp.async.cg.shared.global [%0], [%1], 16;"
                 :: "r"(dst), "l"(__cvta_generic_to_global(src)) : "memory");
}
__device__ __forceinline__ void cpa_commit() {
    asm volatile("cp.async.commit_group;" ::: "memory");
}
template <int N>
__device__ __forceinline__ void cpa_wait() {
    asm volatile("cp.async.wait_group %0;" :: "n"(N) : "memory");
}

// relaxed / acquire global ops
__device__ __forceinline__ void st_rlx_u64(ull* p, ull v) {
    asm volatile("st.relaxed.gpu.global.u64 [%0], %1;" :: "l"(p), "l"(v)
                 : "memory");
}
__device__ __forceinline__ ulonglong2 ld_rlx_v2u64(const ull* p) {
    ulonglong2 v;
    asm volatile("ld.relaxed.gpu.global.v2.u64 {%0,%1}, [%2];"
                 : "=l"(v.x), "=l"(v.y) : "l"(p) : "memory");
    return v;
}
__device__ __forceinline__ void st_rlx_u32(uint32_t* p, uint32_t v) {
    asm volatile("st.relaxed.gpu.global.u32 [%0], %1;" :: "l"(p), "r"(v)
                 : "memory");
}
__device__ __forceinline__ uint32_t ld_acq_u32(const uint32_t* p) {
    uint32_t v;
    asm volatile("ld.acquire.gpu.global.u32 %0, [%1];" : "=r"(v) : "l"(p)
                 : "memory");
    return v;
}

// bf16 hi/lo split of a float
__device__ __forceinline__ void bsplit(float v, __nv_bfloat16& h, __nv_bfloat16& l) {
    h = __float2bfloat16(v);
    l = __float2bfloat16(v - __bfloat162float(h));
}

// ---------------------------------------------------------------------------
// Kernel 0a: convert x -> bf16 hi/lo planes
// ---------------------------------------------------------------------------
__global__ void __launch_bounds__(256) convert_x_kernel(const float* __restrict__ x)
{
    const size_t n4 = (size_t)MTOT * KIN / 4;
    for (size_t i = (size_t)blockIdx.x * blockDim.x + threadIdx.x; i < n4;
         i += (size_t)gridDim.x * blockDim.x) {
        float4 v = ((const float4*)x)[i];
        __nv_bfloat16 h0, h1, h2, h3, l0, l1, l2, l3;
        bsplit(v.x, h0, l0); bsplit(v.y, h1, l1);
        bsplit(v.z, h2, l2); bsplit(v.w, h3, l3);
        __nv_bfloat162 ph0 = {h0, h1}, ph1 = {h2, h3};
        __nv_bfloat162 pl0 = {l0, l1}, pl1 = {l2, l3};
        uint2 uh = {*(uint32_t*)&ph0, *(uint32_t*)&ph1};
        uint2 ul = {*(uint32_t*)&pl0, *(uint32_t*)&pl1};
        ((uint2*)g_xh)[i] = uh;
        ((uint2*)g_xl)[i] = ul;
    }
}

// ---------------------------------------------------------------------------
// Kernel 0b: convert Wi -> bf16 hi/lo, bias, clear tags + preact flags
// ---------------------------------------------------------------------------
__global__ void __launch_bounds__(256) convert_w_kernel(
    const float* __restrict__ Wi, const float* __restrict__ bi,
    const float* __restrict__ bh)
{
    const size_t tid = (size_t)blockIdx.x * blockDim.x + threadIdx.x;
    const size_t n4 = (size_t)G4H * KIN / 4;   // 65536
    if (tid < n4) {
        float4 v = ((const float4*)Wi)[tid];
        __nv_bfloat16 h0, h1, h2, h3, l0, l1, l2, l3;
        bsplit(v.x, h0, l0); bsplit(v.y, h1, l1);
        bsplit(v.z, h2, l2); bsplit(v.w, h3, l3);
        __nv_bfloat162 ph0 = {h0, h1}, ph1 = {h2, h3};
        __nv_bfloat162 pl0 = {l0, l1}, pl1 = {l2, l3};
        uint2 uh = {*(uint32_t*)&ph0, *(uint32_t*)&ph1};
        uint2 ul = {*(uint32_t*)&pl0, *(uint32_t*)&pl1};
        ((uint2*)g_wih)[tid] = uh;
        ((uint2*)g_wil)[tid] = ul;
    }
    if (tid < G4H) g_bias[tid] = bi[tid] + bh[tid];
    if (tid < 8 * 2 * 8 * 256) ((ull*)g_hex)[tid] = 0ull;
    if (tid < SEQ) g_pflag[tid] = 0u;
}

// ---------------------------------------------------------------------------
// FUSED kernel: 128 blocks x 384 threads.
//   warps 0-7  (u<256):  recurrent LSTM (proven round-15 body; barriers -> id 1)
//   warps 8-11 (u>=256): input-GEMM worker; block b computes timesteps
//                        t = b, b+128, ... and publishes g_pflag[t] = t+1.
// Rec polls flags with ld.acquire before each preact prefetch.
// ---------------------------------------------------------------------------
#define HBP 272    // bf16 row pad for rec tiles
#define XPAD 264   // x smem row pad (528B rows, coprime banks)
#define XPLANE (64 * XPAD)
#define FSM ((2 * XPLANE + 2 * 2 * 64 * 40) * 2)   // 88064 bytes dynamic

__global__ void __launch_bounds__(384, 1) lstm_fused(
    const float* __restrict__ h0, const float* __restrict__ c0,
    const float* __restrict__ Wh, float* __restrict__ out)
{
    extern __shared__ __nv_bfloat16 gsm[];     // gemm region (dynamic)
    __nv_bfloat16* xs = gsm;                   // [2][64][XPAD]
    __nv_bfloat16* ws = gsm + 2 * XPLANE;      // [2 stage][2 plane][64][40]

    __shared__ __nv_bfloat16 wsh[16][HBP], wsl[16][HBP];   // rec Wh staging
    __shared__ __nv_bfloat16 hbh[8][HBP], hbl[8][HBP];     // rec h hi/lo
    __shared__ float creds[4][2][4][33];

    const int u = threadIdx.x;

    if (u < 256) {
        // ================== RECURRENT PART (warps 0-7) ==================
        const int jb  = blockIdx.x & 15;
        const int bb  = blockIdx.x >> 4;
        const int j0  = jb * 16;
        const int b0  = bb * 8;

        const int wid  = u >> 5;
        const int l    = u & 31;
        const int gate = wid & 3;
        const int kh   = wid >> 2;

        const int pb = u >> 5;
        const int pj = (u & 31) * 8;

        // stage Wh -> registers as mma A-fragments (hi/lo), 4 passes
        uint32_t ah[8][4], al[8][4];
        for (int pass = 0; pass < 4; pass++) {
            for (int idx = u; idx < 16 * 256; idx += 256) {
                int r = idx >> 8, c = idx & 255;
                float w = Wh[((size_t)pass * HID + j0 + r) * HID + c];
                __nv_bfloat16 hh, ll;
                bsplit(w, hh, ll);
                wsh[r][c] = hh;
                wsl[r][c] = ll;
            }
            barn(1, 256);
            if (gate == pass) {
#pragma unroll
                for (int ks = 0; ks < 8; ks++) {
                    const int kc = (kh * 8 + ks) * 16;
                    ldm_x4(ah[ks], smem_u32(&wsh[l & 15][kc + (l >> 4) * 8]));
                    ldm_x4(al[ks], smem_u32(&wsl[l & 15][kc + (l >> 4) * 8]));
                }
            }
            barn(1, 256);
        }

        const int tb = u >> 4;
        const int tj = u & 15;
        float cst = 0.f, hlast = 0.f;
        if (u < 128) cst = c0[(b0 + tb) * HID + j0 + tj];

        // preload h0 -> bf16 hi/lo
        {
            float4 v0 = *(const float4*)&h0[(size_t)(b0 + pb) * HID + pj];
            float4 v1 = *(const float4*)&h0[(size_t)(b0 + pb) * HID + pj + 4];
            float v[8] = {v0.x, v0.y, v0.z, v0.w, v1.x, v1.y, v1.z, v1.w};
            uint32_t hp[4], lp[4];
#pragma unroll
            for (int i = 0; i < 4; i++) {
                __nv_bfloat16 e0, e1, f0, f1;
                bsplit(v[2 * i], e0, f0); bsplit(v[2 * i + 1], e1, f1);
                __nv_bfloat162 he = {e0, e1}, le = {f0, f1};
                hp[i] = *(uint32_t*)&he; lp[i] = *(uint32_t*)&le;
            }
            *(uint4*)&hbh[pb][pj] = make_uint4(hp[0], hp[1], hp[2], hp[3]);
            *(uint4*)&hbl[pb][pj] = make_uint4(lp[0], lp[1], lp[2], lp[3]);
        }

        // preact for t=0: wait for GEMM flag 0, then prefetch
        float px0 = 0.f, px1 = 0.f, px2 = 0.f, px3 = 0.f;
        if (u < 128) {
            while (ld_acq_u32(&g_pflag[0]) == 0u) {}
            const float* pp = g_preact + ((size_t)(b0 + tb)) * G4H + j0 + tj;
            px0 = pp[0 * HID]; px1 = pp[1 * HID];
            px2 = pp[2 * HID]; px3 = pp[3 * HID];
        }
        barn(1, 256);

        const int glane = (tj & 7) * 4 + (tb >> 1);
        const int greg  = (tb & 1) + 2 * (tj >> 3);

        for (int t = 0; t < SEQ; t++) {
            // tensor-core GEMM: 3 independent bf16x3 accumulator chains
            float c1[4] = {0.f, 0.f, 0.f, 0.f};
            float c2[4] = {0.f, 0.f, 0.f, 0.f};
            float c3[4] = {0.f, 0.f, 0.f, 0.f};
#pragma unroll
            for (int ks = 0; ks < 8; ks++) {
                const int kc = (kh * 8 + ks) * 16;
                uint32_t bh2[2], bl2[2];
                ldm_x2(bh2, smem_u32(&hbh[l & 7][kc + ((l >> 3) & 1) * 8]));
                ldm_x2(bl2, smem_u32(&hbl[l & 7][kc + ((l >> 3) & 1) * 8]));
                mma16816(c1, ah[ks], bh2);
                mma16816(c2, ah[ks], bl2);
                mma16816(c3, al[ks], bh2);
            }
#pragma unroll
            for (int q = 0; q < 4; q++)
                creds[gate][kh][q][l] = c1[q] + c2[q] + c3[q];
            barn(1, 256);

            // gates + publish
            if (u < 128) {
                float p[4];
#pragma unroll
                for (int g = 0; g < 4; g++)
                    p[g] = creds[g][0][greg][glane] + creds[g][1][greg][glane];
                p[0] += px0; p[1] += px1; p[2] += px2; p[3] += px3;

                float it = sigf(p[0]);
                float ft = sigf(p[1]);
                float ot = sigf(p[2]);
                float gt = tanhf_(p[3]);
                cst = cst * ft + it * gt;
                float ht = ot * tanhf_(cst);
                hlast = ht;

                if (t < SEQ - 1) {
                    ull pub = ((ull)(uint32_t)(t + 1) << 32)
                            | (ull)__float_as_uint(ht);
                    st_rlx_u64(&g_hex[bb][(t + 1) & 1][tb][j0 + tj], pub);
                }
                out[((size_t)t * BATCH + b0 + tb) * HID + j0 + tj] = ht;
            }

            // poll preact-ready for t+1, then prefetch (off critical path)
            float nx0 = 0.f, nx1 = 0.f, nx2 = 0.f, nx3 = 0.f;
            if (u < 128) {
                const int tn = (t + 1 < SEQ) ? (t + 1) : t;
                const uint32_t want = (uint32_t)(tn + 1);
                while (ld_acq_u32(&g_pflag[tn]) != want) {}
                const float* pp = g_preact
                    + ((size_t)tn * BATCH + b0 + tb) * G4H + j0 + tj;
                nx0 = pp[0 * HID]; nx1 = pp[1 * HID];
                nx2 = pp[2 * HID]; nx3 = pp[3 * HID];
            }

            // poll h(t+1), convert to bf16 hi/lo, fill smem
            if (t < SEQ - 1) {
                const ull* p = &g_hex[bb][(t + 1) & 1][pb][pj];
                const uint32_t tg = (uint32_t)(t + 1);
                ulonglong2 v0, v1, v2, v3;
                while (true) {
                    v0 = ld_rlx_v2u64(p + 0);
                    v1 = ld_rlx_v2u64(p + 2);
                    v2 = ld_rlx_v2u64(p + 4);
                    v3 = ld_rlx_v2u64(p + 6);
                    bool ok = ((uint32_t)(v0.x >> 32) == tg) &
                              ((uint32_t)(v0.y >> 32) == tg) &
                              ((uint32_t)(v1.x >> 32) == tg) &
                              ((uint32_t)(v1.y >> 32) == tg) &
                              ((uint32_t)(v2.x >> 32) == tg) &
                              ((uint32_t)(v2.y >> 32) == tg) &
                              ((uint32_t)(v3.x >> 32) == tg) &
                              ((uint32_t)(v3.y >> 32) == tg);
                    if (ok) break;
                }
                float v[8] = {
                    __uint_as_float((uint32_t)v0.x), __uint_as_float((uint32_t)v0.y),
                    __uint_as_float((uint32_t)v1.x), __uint_as_float((uint32_t)v1.y),
                    __uint_as_float((uint32_t)v2.x), __uint_as_float((uint32_t)v2.y),
                    __uint_as_float((uint32_t)v3.x), __uint_as_float((uint32_t)v3.y)};
                uint32_t hp[4], lp[4];
#pragma unroll
                for (int i = 0; i < 4; i++) {
                    __nv_bfloat16 e0, e1, f0, f1;
                    bsplit(v[2 * i], e0, f0); bsplit(v[2 * i + 1], e1, f1);
                    __nv_bfloat162 he = {e0, e1}, le = {f0, f1};
                    hp[i] = *(uint32_t*)&he; lp[i] = *(uint32_t*)&le;
                }
                *(uint4*)&hbh[pb][pj] = make_uint4(hp[0], hp[1], hp[2], hp[3]);
                *(uint4*)&hbl[pb][pj] = make_uint4(lp[0], lp[1], lp[2], lp[3]);
            }
            barn(1, 256);

            px0 = nx0; px1 = nx1; px2 = nx2; px3 = nx3;
        }

        if (u < 128) {
            const size_t base = (size_t)SEQ * BATCH * HID;
            const int idx = (b0 + tb) * HID + j0 + tj;
            out[base + idx]               = hlast;
            out[base + BATCH * HID + idx] = cst;
        }
    } else {
        // ================== GEMM WORKER (warps 8-11) ==================
        const int gu = u - 256;          // 0..127
        const int gw = gu >> 5, gl = gu & 31;
        const int wm = gw & 1, wn = gw >> 1;

        for (int t = blockIdx.x; t < SEQ; t += 128) {
            // ---- load x[t] hi/lo planes into smem (once per unit) ----
            for (int i = gu; i < 4096; i += 128) {
                int pl = i >> 11;
                int j  = i & 2047;
                int r  = j >> 5, c = j & 31;
                const __nv_bfloat16* src = (pl ? g_xl : g_xh)
                    + ((size_t)t * 64 + r) * KIN + c * 8;
                cpa16(smem_u32(xs + pl * XPLANE + r * XPAD + c * 8), src);
            }
            cpa_commit();
            cpa_wait<0>();
            barn(2, 128);

            for (int nb = 0; nb < 16; nb++) {
                const int n0 = nb * 64;
                float acc[2][4][4];
#pragma unroll
                for (int mi = 0; mi < 2; mi++)
#pragma unroll
                    for (int ni = 0; ni < 4; ni++)
#pragma unroll
                        for (int q = 0; q < 4; q++) acc[mi][ni][q] = 0.f;

                auto issue_wi = [&](int kc, int st) {
#pragma unroll
                    for (int k = 0; k < 4; k++) {
                        int i = gu + k * 128;            // 0..511
                        int pl = i >> 8;
                        int j  = i & 255;
                        int r  = j >> 2, q = j & 3;
                        const __nv_bfloat16* src = (pl ? g_wil : g_wih)
                            + (size_t)(n0 + r) * KIN + kc * 32 + q * 8;
                        cpa16(smem_u32(ws + ((st * 2 + pl) * 64 + r) * 40 + q * 8),
                              src);
                    }
                    cpa_commit();
                };

                issue_wi(0, 0);
                for (int kc = 0; kc < 8; kc++) {
                    const int st = kc & 1;
                    if (kc < 7) { issue_wi(kc + 1, st ^ 1); cpa_wait<1>(); }
                    else        { cpa_wait<0>(); }
                    barn(2, 128);

#pragma unroll
                    for (int ks = 0; ks < 2; ks++) {
                        uint32_t afh[2][4], afl[2][4], bfh[4][2], bfl[4][2];
#pragma unroll
                        for (int mi = 0; mi < 2; mi++) {
                            const int row = wm * 32 + mi * 16 + (gl & 15);
                            const int col = kc * 32 + ks * 16 + (gl >> 4) * 8;
                            ldm_x4(afh[mi], smem_u32(xs + row * XPAD + col));
                            ldm_x4(afl[mi], smem_u32(xs + XPLANE + row * XPAD + col));
                        }
#pragma unroll
                        for (int ni = 0; ni < 4; ni++) {
                            const int row = wn * 32 + ni * 8 + (gl & 7);
                            const int col = ks * 16 + ((gl >> 3) & 1) * 8;
                            ldm_x2(bfh[ni], smem_u32(
                                ws + ((st * 2 + 0) * 64 + row) * 40 + col));
                            ldm_x2(bfl[ni], smem_u32(
                                ws + ((st * 2 + 1) * 64 + row) * 40 + col));
                        }
#pragma unroll
                        for (int mi = 0; mi < 2; mi++)
#pragma unroll
                            for (int ni = 0; ni < 4; ni++) {
                                mma16816(acc[mi][ni], afh[mi], bfh[ni]);
                                mma16816(acc[mi][ni], afh[mi], bfl[ni]);
                                mma16816(acc[mi][ni], afl[mi], bfh[ni]);
                            }
                    }
                    barn(2, 128);
                }

                // epilogue: bias + store
#pragma unroll
                for (int ni = 0; ni < 4; ni++) {
                    const int gn = n0 + wn * 32 + ni * 8 + (gl & 3) * 2;
                    const float b0v = g_bias[gn], b1v = g_bias[gn + 1];
#pragma unroll
                    for (int mi = 0; mi < 2; mi++) {
                        const size_t gm = (size_t)t * 64 + wm * 32 + mi * 16
                                        + (gl >> 2);
                        float2 v0 = {acc[mi][ni][0] + b0v, acc[mi][ni][1] + b1v};
                        float2 v1 = {acc[mi][ni][2] + b0v, acc[mi][ni][3] + b1v};
                        *(float2*)&g_preact[gm * G4H + gn]       = v0;
                        *(float2*)&g_preact[(gm + 8) * G4H + gn] = v1;
                    }
                }
            }

            // publish completion of timestep t
            barn(2, 128);
            if (gu == 0) {
                __threadfence();   // cumulative: orders all warps' epilogue STGs
                st_rlx_u32(&g_pflag[t], (uint32_t)(t + 1));
            }
        }
    }
}

// ---------------------------------------------------------------------------
extern "C" void kernel_launch(void* const* d_in, const int* in_sizes, int n_in,
                              void* d_out, int out_size)
{
    const float* x  = (const float*)d_in[0];
    const float* h0 = (const float*)d_in[1];
    const float* c0 = (const float*)d_in[2];
    const float* Wi = (const float*)d_in[3];
    const float* bi = (const float*)d_in[4];
    const float* Wh = (const float*)d_in[5];
    const float* bh = (const float*)d_in[6];
    float* out = (float*)d_out;

    cudaFuncSetAttribute(lstm_fused,
                         cudaFuncAttributeMaxDynamicSharedMemorySize, FSM);

    convert_x_kernel<<<8192, 256>>>(x);
    convert_w_kernel<<<256, 256>>>(Wi, bi, bh);

    lstm_fused<<<128, 384, FSM>>>(h0, c0, Wh, out);
}